// round 1
// baseline (speedup 1.0000x reference)
#include <cuda_runtime.h>

#define NTHREADS 256
#define ROWS_PER_BLOCK 64
#define HDIM 1024

// Each block: 256 threads, each thread owns 4 contiguous output columns
// (weights held in registers), loops over 64 rows.
// Phase 1: threads 0..63 compute per-row scalars (pos, sin/cos euler, gripper)
// into shared memory. Phase 2: all threads compute h, block-reduce LayerNorm
// stats (double-buffered partials => 1 __syncthreads per row), write float4.

__global__ __launch_bounds__(NTHREADS, 2)
void action_embed_kernel(const float* __restrict__ actions,
                         const float* __restrict__ pos_W,
                         const float* __restrict__ pos_b,
                         const float* __restrict__ rot_W,
                         const float* __restrict__ rot_b,
                         const float* __restrict__ open_emb,
                         const float* __restrict__ ln_g,
                         const float* __restrict__ ln_b,
                         float* __restrict__ out,
                         int B)
{
    __shared__ float s_scal[ROWS_PER_BLOCK][10];
    __shared__ float s_part[2][2][8];   // [parity][sum|sumsq][warp]

    const int tid  = threadIdx.x;
    const int col0 = tid * 4;
    const int row0 = blockIdx.x * ROWS_PER_BLOCK;
    const int lane = tid & 31;
    const int warp = tid >> 5;

    // ---- weights into registers (one-time per block; L2-resident) ----
    const float4 P0 = *(const float4*)(pos_W + 0 * HDIM + col0);
    const float4 P1 = *(const float4*)(pos_W + 1 * HDIM + col0);
    const float4 P2 = *(const float4*)(pos_W + 2 * HDIM + col0);
    const float4 R0 = *(const float4*)(rot_W + 0 * HDIM + col0);
    const float4 R1 = *(const float4*)(rot_W + 1 * HDIM + col0);
    const float4 R2 = *(const float4*)(rot_W + 2 * HDIM + col0);
    const float4 R3 = *(const float4*)(rot_W + 3 * HDIM + col0);
    const float4 R4 = *(const float4*)(rot_W + 4 * HDIM + col0);
    const float4 R5 = *(const float4*)(rot_W + 5 * HDIM + col0);
    const float4 pb = *(const float4*)(pos_b + col0);
    const float4 rb = *(const float4*)(rot_b + col0);
    const float4 E0 = *(const float4*)(open_emb + 0 * HDIM + col0);
    const float4 E1 = *(const float4*)(open_emb + 1 * HDIM + col0);
    const float4 G  = *(const float4*)(ln_g + col0);
    const float4 LB = *(const float4*)(ln_b + col0);
    float4 Bb;   // combined biases
    Bb.x = pb.x + rb.x; Bb.y = pb.y + rb.y; Bb.z = pb.z + rb.z; Bb.w = pb.w + rb.w;

    // ---- phase 1: per-row scalars ----
    const int rows_here = min(ROWS_PER_BLOCK, B - row0);
    if (tid < rows_here) {
        const int row = row0 + tid;
        const float4 a = *(const float4*)(actions + row * 8);      // p0 p1 p2 qx
        const float4 q = *(const float4*)(actions + row * 8 + 4);  // qy qz qw grip
        float x = a.w, y = q.x, z = q.y, w = q.z;
        const float inv = rsqrtf(x * x + y * y + z * z + w * w);
        x *= inv; y *= inv; z *= inv; w *= inv;

        const float roll = atan2f(2.0f * (w * x + y * z), 1.0f - 2.0f * (x * x + y * y));
        float t = 2.0f * (w * y - z * x);
        t = fminf(1.0f, fmaxf(-1.0f, t));
        const float pitch = asinf(t);
        const float yaw = atan2f(2.0f * (w * z + x * y), 1.0f - 2.0f * (y * y + z * z));

        float sr, cr, sp, cp, sy, cy;
        sincosf(roll,  &sr, &cr);
        sincosf(pitch, &sp, &cp);
        sincosf(yaw,   &sy, &cy);

        s_scal[tid][0] = a.x;  s_scal[tid][1] = a.y;  s_scal[tid][2] = a.z;
        s_scal[tid][3] = sr;   s_scal[tid][4] = sp;   s_scal[tid][5] = sy;
        s_scal[tid][6] = cr;   s_scal[tid][7] = cp;   s_scal[tid][8] = cy;
        s_scal[tid][9] = q.w;  // gripper flag (0.0 or 1.0)
    }
    __syncthreads();

    // ---- phase 2: row loop ----
    for (int r = 0; r < rows_here; ++r) {
        const float a0 = s_scal[r][0], a1 = s_scal[r][1], a2 = s_scal[r][2];
        const float sr = s_scal[r][3], sp = s_scal[r][4], sy = s_scal[r][5];
        const float cr = s_scal[r][6], cp = s_scal[r][7], cy = s_scal[r][8];
        const bool sel = (s_scal[r][9] != 0.0f);

        float4 h;
        h.x = Bb.x + (sel ? E1.x : E0.x);
        h.y = Bb.y + (sel ? E1.y : E0.y);
        h.z = Bb.z + (sel ? E1.z : E0.z);
        h.w = Bb.w + (sel ? E1.w : E0.w);

        h.x = fmaf(a0, P0.x, h.x); h.y = fmaf(a0, P0.y, h.y); h.z = fmaf(a0, P0.z, h.z); h.w = fmaf(a0, P0.w, h.w);
        h.x = fmaf(a1, P1.x, h.x); h.y = fmaf(a1, P1.y, h.y); h.z = fmaf(a1, P1.z, h.z); h.w = fmaf(a1, P1.w, h.w);
        h.x = fmaf(a2, P2.x, h.x); h.y = fmaf(a2, P2.y, h.y); h.z = fmaf(a2, P2.z, h.z); h.w = fmaf(a2, P2.w, h.w);
        h.x = fmaf(sr, R0.x, h.x); h.y = fmaf(sr, R0.y, h.y); h.z = fmaf(sr, R0.z, h.z); h.w = fmaf(sr, R0.w, h.w);
        h.x = fmaf(sp, R1.x, h.x); h.y = fmaf(sp, R1.y, h.y); h.z = fmaf(sp, R1.z, h.z); h.w = fmaf(sp, R1.w, h.w);
        h.x = fmaf(sy, R2.x, h.x); h.y = fmaf(sy, R2.y, h.y); h.z = fmaf(sy, R2.z, h.z); h.w = fmaf(sy, R2.w, h.w);
        h.x = fmaf(cr, R3.x, h.x); h.y = fmaf(cr, R3.y, h.y); h.z = fmaf(cr, R3.z, h.z); h.w = fmaf(cr, R3.w, h.w);
        h.x = fmaf(cp, R4.x, h.x); h.y = fmaf(cp, R4.y, h.y); h.z = fmaf(cp, R4.z, h.z); h.w = fmaf(cp, R4.w, h.w);
        h.x = fmaf(cy, R5.x, h.x); h.y = fmaf(cy, R5.y, h.y); h.z = fmaf(cy, R5.z, h.z); h.w = fmaf(cy, R5.w, h.w);

        // LN stats: block reduction of sum / sumsq
        float s  = (h.x + h.y) + (h.z + h.w);
        float q2 = fmaf(h.x, h.x, h.y * h.y) + fmaf(h.z, h.z, h.w * h.w);
        #pragma unroll
        for (int o = 16; o > 0; o >>= 1) {
            s  += __shfl_xor_sync(0xFFFFFFFFu, s,  o);
            q2 += __shfl_xor_sync(0xFFFFFFFFu, q2, o);
        }
        const int par = r & 1;
        if (lane == 0) {
            s_part[par][0][warp] = s;
            s_part[par][1][warp] = q2;
        }
        __syncthreads();
        float S = 0.0f, Q = 0.0f;
        #pragma unroll
        for (int i = 0; i < 8; ++i) {
            S += s_part[par][0][i];
            Q += s_part[par][1][i];
        }
        const float mu   = S * (1.0f / HDIM);
        const float var  = fmaf(-mu, mu, Q * (1.0f / HDIM));
        const float rstd = rsqrtf(var + 1e-12f);

        float4 o;
        const float tx = rstd * G.x, ty = rstd * G.y, tz = rstd * G.z, tw = rstd * G.w;
        o.x = fmaf(h.x - mu, tx, LB.x);
        o.y = fmaf(h.y - mu, ty, LB.y);
        o.z = fmaf(h.z - mu, tz, LB.z);
        o.w = fmaf(h.w - mu, tw, LB.w);

        *(float4*)(out + (size_t)(row0 + r) * HDIM + col0) = o;
    }
}

extern "C" void kernel_launch(void* const* d_in, const int* in_sizes, int n_in,
                              void* d_out, int out_size)
{
    const float* actions  = (const float*)d_in[0];
    const float* pos_W    = (const float*)d_in[1];
    const float* pos_b    = (const float*)d_in[2];
    const float* rot_W    = (const float*)d_in[3];
    const float* rot_b    = (const float*)d_in[4];
    const float* open_emb = (const float*)d_in[5];
    const float* ln_g     = (const float*)d_in[6];
    const float* ln_b     = (const float*)d_in[7];
    float* out = (float*)d_out;

    const int B = in_sizes[0] / 8;
    const int grid = (B + ROWS_PER_BLOCK - 1) / ROWS_PER_BLOCK;

    action_embed_kernel<<<grid, NTHREADS>>>(actions, pos_W, pos_b, rot_W, rot_b,
                                            open_emb, ln_g, ln_b, out, B);
}

// round 2
// speedup vs baseline: 2.1058x; 2.1058x over previous
#include <cuda_runtime.h>

#define NTHREADS 256
#define ROWS_PER_BLOCK 64
#define HDIM 1024
#define NFEAT 11           // p0 p1 p2 sr sp sy cr cp cy 1 sel
#define NGRAM 66           // upper triangle incl diag of 11x11
#define NSTAT 77           // 66 gram + 11 colsums

// scratch for gram matrix + column sums (written by gram_kernel each launch)
__device__ float g_stats[NSTAT];

typedef unsigned long long u64;

__device__ __forceinline__ u64 fma2(u64 a, u64 b, u64 c) {
    u64 d; asm("fma.rn.f32x2 %0,%1,%2,%3;" : "=l"(d) : "l"(a), "l"(b), "l"(c)); return d;
}
__device__ __forceinline__ u64 mul2(u64 a, u64 b) {
    u64 d; asm("mul.rn.f32x2 %0,%1,%2;" : "=l"(d) : "l"(a), "l"(b)); return d;
}
__device__ __forceinline__ u64 pk2(float a, float b) {
    u64 r; asm("mov.b64 %0,{%1,%2};" : "=l"(r) : "f"(a), "f"(b)); return r;
}

// ---------------------------------------------------------------------------
// Setup kernel: compute G = M^T M (upper triangle) and colsums of M.
// One warp per output value; each warp scans 1024 columns (coalesced).
// ---------------------------------------------------------------------------
__device__ __forceinline__ float colv(int k, int j,
                                      const float* __restrict__ pos_W,
                                      const float* __restrict__ pos_b,
                                      const float* __restrict__ rot_W,
                                      const float* __restrict__ rot_b,
                                      const float* __restrict__ open_emb)
{
    if (k < 3)  return pos_W[k * HDIM + j];
    if (k < 9)  return rot_W[(k - 3) * HDIM + j];
    if (k == 9) return pos_b[j] + rot_b[j] + open_emb[j];            // base column
    return open_emb[HDIM + j] - open_emb[j];                         // delta column
}

__global__ void gram_kernel(const float* __restrict__ pos_W,
                            const float* __restrict__ pos_b,
                            const float* __restrict__ rot_W,
                            const float* __restrict__ rot_b,
                            const float* __restrict__ open_emb)
{
    const int w    = (blockIdx.x * blockDim.x + threadIdx.x) >> 5;
    const int lane = threadIdx.x & 31;
    if (w >= NSTAT) return;

    int k = 0, l = -1;
    if (w < NGRAM) {
        int rem = w;
        for (k = 0; k < NFEAT; ++k) {
            int len = NFEAT - k;
            if (rem < len) { l = k + rem; break; }
            rem -= len;
        }
    } else {
        k = w - NGRAM;            // colsum of column k
    }

    float acc = 0.0f;
    for (int j = lane; j < HDIM; j += 32) {
        const float a = colv(k, j, pos_W, pos_b, rot_W, rot_b, open_emb);
        const float b = (l >= 0) ? colv(l, j, pos_W, pos_b, rot_W, rot_b, open_emb) : 1.0f;
        acc = fmaf(a, b, acc);
    }
    #pragma unroll
    for (int o = 16; o > 0; o >>= 1)
        acc += __shfl_xor_sync(0xFFFFFFFFu, acc, o);
    if (lane == 0) g_stats[w] = acc;
}

// ---------------------------------------------------------------------------
// Main kernel. Phase 1: threads 0..63 compute per-row feature vector,
// analytic mu/rstd from G, broadcast as (v,v) float2 pairs into shared.
// Phase 2: pure streaming — packed f32x2 FMAs, float4 streaming store.
// No shuffles / barriers inside the row loop.
// ---------------------------------------------------------------------------
__global__ __launch_bounds__(NTHREADS, 3)
void action_embed_kernel(const float* __restrict__ actions,
                         const float* __restrict__ pos_W,
                         const float* __restrict__ pos_b,
                         const float* __restrict__ rot_W,
                         const float* __restrict__ rot_b,
                         const float* __restrict__ open_emb,
                         const float* __restrict__ ln_g,
                         const float* __restrict__ ln_b,
                         float* __restrict__ out,
                         int B)
{
    __shared__ float sG[NSTAT];
    __shared__ u64  s_row[ROWS_PER_BLOCK][12];   // 9 feats + sel + (-mu) + rstd, each (v,v)

    const int tid  = threadIdx.x;
    const int col0 = tid * 4;
    const int row0 = blockIdx.x * ROWS_PER_BLOCK;

    if (tid < NSTAT) sG[tid] = g_stats[tid];

    // ---- per-thread weight registers, packed as f32x2 pairs ----
    const float4 P0 = *(const float4*)(pos_W + 0 * HDIM + col0);
    const float4 P1 = *(const float4*)(pos_W + 1 * HDIM + col0);
    const float4 P2 = *(const float4*)(pos_W + 2 * HDIM + col0);
    const float4 R0 = *(const float4*)(rot_W + 0 * HDIM + col0);
    const float4 R1 = *(const float4*)(rot_W + 1 * HDIM + col0);
    const float4 R2 = *(const float4*)(rot_W + 2 * HDIM + col0);
    const float4 R3 = *(const float4*)(rot_W + 3 * HDIM + col0);
    const float4 R4 = *(const float4*)(rot_W + 4 * HDIM + col0);
    const float4 R5 = *(const float4*)(rot_W + 5 * HDIM + col0);
    const float4 pb = *(const float4*)(pos_b + col0);
    const float4 rb = *(const float4*)(rot_b + col0);
    const float4 E0 = *(const float4*)(open_emb + 0 * HDIM + col0);
    const float4 E1 = *(const float4*)(open_emb + 1 * HDIM + col0);
    const float4 Gg = *(const float4*)(ln_g + col0);
    const float4 LB = *(const float4*)(ln_b + col0);

    const u64 P0l = pk2(P0.x, P0.y), P0h = pk2(P0.z, P0.w);
    const u64 P1l = pk2(P1.x, P1.y), P1h = pk2(P1.z, P1.w);
    const u64 P2l = pk2(P2.x, P2.y), P2h = pk2(P2.z, P2.w);
    const u64 R0l = pk2(R0.x, R0.y), R0h = pk2(R0.z, R0.w);
    const u64 R1l = pk2(R1.x, R1.y), R1h = pk2(R1.z, R1.w);
    const u64 R2l = pk2(R2.x, R2.y), R2h = pk2(R2.z, R2.w);
    const u64 R3l = pk2(R3.x, R3.y), R3h = pk2(R3.z, R3.w);
    const u64 R4l = pk2(R4.x, R4.y), R4h = pk2(R4.z, R4.w);
    const u64 R5l = pk2(R5.x, R5.y), R5h = pk2(R5.z, R5.w);
    const u64 BAl = pk2(pb.x + rb.x + E0.x, pb.y + rb.y + E0.y);
    const u64 BAh = pk2(pb.z + rb.z + E0.z, pb.w + rb.w + E0.w);
    const u64 DEl = pk2(E1.x - E0.x, E1.y - E0.y);
    const u64 DEh = pk2(E1.z - E0.z, E1.w - E0.w);
    const u64 Gl  = pk2(Gg.x, Gg.y), Gh = pk2(Gg.z, Gg.w);
    const u64 LBl = pk2(LB.x, LB.y), LBh = pk2(LB.z, LB.w);

    __syncthreads();   // sG visible

    // ---- phase 1: per-row scalars + analytic LN stats ----
    const int rows_here = min(ROWS_PER_BLOCK, B - row0);
    if (tid < rows_here) {
        const int row = row0 + tid;
        const float4 a = *(const float4*)(actions + row * 8);      // p0 p1 p2 qx
        const float4 q = *(const float4*)(actions + row * 8 + 4);  // qy qz qw grip
        float x = a.w, y = q.x, z = q.y, w = q.z;
        const float inv = rsqrtf(x * x + y * y + z * z + w * w);
        x *= inv; y *= inv; z *= inv; w *= inv;

        const float roll = atan2f(2.0f * (w * x + y * z), 1.0f - 2.0f * (x * x + y * y));
        float t = 2.0f * (w * y - z * x);
        t = fminf(1.0f, fmaxf(-1.0f, t));
        const float pitch = asinf(t);
        const float yaw = atan2f(2.0f * (w * z + x * y), 1.0f - 2.0f * (y * y + z * z));

        float sr, cr, sp, cp, sy, cy;
        sincosf(roll,  &sr, &cr);
        sincosf(pitch, &sp, &cp);
        sincosf(yaw,   &sy, &cy);

        float xv[NFEAT] = {a.x, a.y, a.z, sr, sp, sy, cr, cp, cy, 1.0f, q.w};

        // S = x . colsum ;  Q = x^T G x  (upper-triangle storage)
        float S = 0.0f, Q = 0.0f;
        int idx = 0;
        #pragma unroll
        for (int k = 0; k < NFEAT; ++k) {
            float accd = sG[idx++] * xv[k];        // diag term
            float acco = 0.0f;
            #pragma unroll
            for (int l = k + 1; l < NFEAT; ++l)
                acco = fmaf(sG[idx++], xv[l], acco);
            Q = fmaf(xv[k], fmaf(2.0f, acco, accd), Q);
            S = fmaf(xv[k], sG[NGRAM + k], S);
        }
        const float mu   = S * (1.0f / HDIM);
        const float var  = fmaf(-mu, mu, Q * (1.0f / HDIM));
        const float rstd = rsqrtf(var + 1e-12f);

        u64* rrow = s_row[tid];
        #pragma unroll
        for (int k = 0; k < 9; ++k) rrow[k] = pk2(xv[k], xv[k]);
        rrow[9]  = pk2(q.w,  q.w);
        rrow[10] = pk2(-mu,  -mu);
        rrow[11] = pk2(rstd, rstd);
    }
    __syncthreads();

    // ---- phase 2: streaming row loop (no sync, no shuffles) ----
    float* outp = out + (size_t)row0 * HDIM + col0;
    for (int r = 0; r < rows_here; ++r, outp += HDIM) {
        const u64* rr = s_row[r];   // broadcast LDS.64 reads

        u64 hl = fma2(rr[9], DEl, BAl);
        u64 hh = fma2(rr[9], DEh, BAh);
        hl = fma2(rr[0], P0l, hl);  hh = fma2(rr[0], P0h, hh);
        hl = fma2(rr[1], P1l, hl);  hh = fma2(rr[1], P1h, hh);
        hl = fma2(rr[2], P2l, hl);  hh = fma2(rr[2], P2h, hh);
        hl = fma2(rr[3], R0l, hl);  hh = fma2(rr[3], R0h, hh);
        hl = fma2(rr[4], R1l, hl);  hh = fma2(rr[4], R1h, hh);
        hl = fma2(rr[5], R2l, hl);  hh = fma2(rr[5], R2h, hh);
        hl = fma2(rr[6], R3l, hl);  hh = fma2(rr[6], R3h, hh);
        hl = fma2(rr[7], R4l, hl);  hh = fma2(rr[7], R4h, hh);
        hl = fma2(rr[8], R5l, hl);  hh = fma2(rr[8], R5h, hh);

        const u64 rgl = mul2(rr[11], Gl);            // rstd * gamma
        const u64 rgh = mul2(rr[11], Gh);
        const u64 cl  = fma2(rr[10], rgl, LBl);      // lb - mu*rstd*gamma
        const u64 ch  = fma2(rr[10], rgh, LBh);
        const u64 ol  = fma2(hl, rgl, cl);
        const u64 oh  = fma2(hh, rgh, ch);

        union { u64 u[2]; float4 f; } cvt;
        cvt.u[0] = ol; cvt.u[1] = oh;
        __stcs((float4*)outp, cvt.f);
    }
}

extern "C" void kernel_launch(void* const* d_in, const int* in_sizes, int n_in,
                              void* d_out, int out_size)
{
    const float* actions  = (const float*)d_in[0];
    const float* pos_W    = (const float*)d_in[1];
    const float* pos_b    = (const float*)d_in[2];
    const float* rot_W    = (const float*)d_in[3];
    const float* rot_b    = (const float*)d_in[4];
    const float* open_emb = (const float*)d_in[5];
    const float* ln_g     = (const float*)d_in[6];
    const float* ln_b     = (const float*)d_in[7];
    float* out = (float*)d_out;

    const int B = in_sizes[0] / 8;

    // 77 warps of work -> 20 blocks x 128 threads
    gram_kernel<<<20, 128>>>(pos_W, pos_b, rot_W, rot_b, open_emb);

    const int grid = (B + ROWS_PER_BLOCK - 1) / ROWS_PER_BLOCK;
    action_embed_kernel<<<grid, NTHREADS>>>(actions, pos_W, pos_b, rot_W, rot_b,
                                            open_emb, ln_g, ln_b, out, B);
}